// round 2
// baseline (speedup 1.0000x reference)
#include <cuda_runtime.h>

// ---------------------------------------------------------------------------
// GIN_LCG: 4 iterations of literal/clause message passing.
//   D = 256 everywhere. L=100000, C=50000, E=300000 (read from in_sizes).
// Output layout: l_embs [5][L][256] followed by c_embs [5][C][256], fp32.
// ---------------------------------------------------------------------------

#define DD 256
#define MAX_L 100000
#define MAX_C 50000

typedef unsigned long long ull;

// -------------------- f32x2 packed-FMA helpers (sm_103a) -------------------
__device__ __forceinline__ ull pack2(float lo, float hi) {
    ull r; asm("mov.b64 %0, {%1, %2};" : "=l"(r) : "f"(lo), "f"(hi)); return r;
}
__device__ __forceinline__ void unpack2(ull v, float& lo, float& hi) {
    asm("mov.b64 {%0, %1}, %2;" : "=f"(lo), "=f"(hi) : "l"(v));
}
__device__ __forceinline__ ull ffma2(ull a, ull b, ull c) {
    ull d; asm("fma.rn.f32x2 %0, %1, %2, %3;" : "=l"(d) : "l"(a), "l"(b), "l"(c));
    return d;
}

// -------------------- scratch (device globals; no allocs allowed) ----------
__device__ float g_hid  [(size_t)MAX_L * DD];  // hidden activations (reused)
__device__ float g_lmsg [(size_t)MAX_L * DD];  // l2c message features
__device__ float g_cmsg [(size_t)MAX_C * DD];  // c2l message features
__device__ float g_l2l  [(size_t)MAX_L * DD];  // l2l messages
__device__ float g_aggc [(size_t)MAX_C * DD];  // clause-side aggregation
__device__ float g_aggl [(size_t)MAX_L * DD];  // literal-side aggregation

// -------------------- GEMM: C[M,256] = act(A @ W + b) ----------------------
// A is given as up to 3 row-major [M,256] segments concatenated along K.
// W row-major [K,256]. row_xor=1 implements the literal<->negation flip.
struct GemmParams {
    const float* A0; const float* A1; const float* A2;
    const float* W;  const float* bias;
    float* C;
    int M, K, row_xor, relu;
};

__global__ __launch_bounds__(256, 2)
void gemm_kernel(GemmParams p) {
    constexpr int BM = 128, BN = 128, BK = 16;
    __shared__ float As[BK][BM + 4];   // transposed A tile
    __shared__ float Bs[BK][BN];

    const int tid = threadIdx.x;
    const int tx  = tid & 15;          // 0..15 -> column group (8 cols)
    const int ty  = tid >> 4;          // 0..15 -> row group (8 rows)
    const int colBase = blockIdx.x * BN;   // grid.x = 2
    const int rowBase = blockIdx.y * BM;   // grid.y = ceil(M/128)

    ull acc[8][4];
    #pragma unroll
    for (int i = 0; i < 8; i++)
        #pragma unroll
        for (int j = 0; j < 4; j++) acc[i][j] = 0ULL;   // {0.0f, 0.0f}

    const int nt = p.K / BK;

    // global-load index decomposition (256 threads)
    const int a_row = tid >> 2;        // 0..63  (two passes -> 128 rows)
    const int a_c4  = tid & 3;         // float4 slot within the 16-wide k strip
    const int b_k   = tid >> 5;        // 0..7   (two passes -> 16 k rows)
    const int b_n4  = tid & 31;        // float4 slot within 128 cols

    float4 aReg[2], bReg[2];

    auto loadTile = [&](int t) {
        const int k0  = t * BK;
        const int seg = k0 >> 8;
        const float* Aseg = (seg == 0) ? p.A0 : ((seg == 1) ? p.A1 : p.A2);
        const int kcol = (k0 & 255) + a_c4 * 4;
        #pragma unroll
        for (int i = 0; i < 2; i++) {
            const int r = rowBase + a_row + i * 64;
            if (r < p.M) {
                const int rg = r ^ p.row_xor;
                aReg[i] = *(const float4*)(Aseg + (size_t)rg * DD + kcol);
            } else {
                aReg[i] = make_float4(0.f, 0.f, 0.f, 0.f);
            }
        }
        #pragma unroll
        for (int i = 0; i < 2; i++) {
            const int kk = k0 + b_k + i * 8;
            bReg[i] = *(const float4*)(p.W + (size_t)kk * DD + colBase + b_n4 * 4);
        }
    };
    auto storeTile = [&]() {
        #pragma unroll
        for (int i = 0; i < 2; i++) {
            const int r = a_row + i * 64;
            As[a_c4 * 4 + 0][r] = aReg[i].x;
            As[a_c4 * 4 + 1][r] = aReg[i].y;
            As[a_c4 * 4 + 2][r] = aReg[i].z;
            As[a_c4 * 4 + 3][r] = aReg[i].w;
        }
        #pragma unroll
        for (int i = 0; i < 2; i++)
            *(float4*)(&Bs[b_k + i * 8][b_n4 * 4]) = bReg[i];
    };

    loadTile(0);
    storeTile();
    __syncthreads();

    for (int t = 0; t < nt; t++) {
        if (t + 1 < nt) loadTile(t + 1);
        #pragma unroll
        for (int k = 0; k < BK; k++) {
            float a[8];
            float4 av0 = *(float4*)&As[k][ty * 8];
            float4 av1 = *(float4*)&As[k][ty * 8 + 4];
            a[0] = av0.x; a[1] = av0.y; a[2] = av0.z; a[3] = av0.w;
            a[4] = av1.x; a[5] = av1.y; a[6] = av1.z; a[7] = av1.w;
            longlong2 bv0 = *(longlong2*)&Bs[k][tx * 8];
            longlong2 bv1 = *(longlong2*)&Bs[k][tx * 8 + 4];
            ull b[4];
            b[0] = (ull)bv0.x; b[1] = (ull)bv0.y;
            b[2] = (ull)bv1.x; b[3] = (ull)bv1.y;
            #pragma unroll
            for (int i = 0; i < 8; i++) {
                ull ap = pack2(a[i], a[i]);
                #pragma unroll
                for (int j = 0; j < 4; j++)
                    acc[i][j] = ffma2(ap, b[j], acc[i][j]);
            }
        }
        __syncthreads();
        if (t + 1 < nt) { storeTile(); __syncthreads(); }
    }

    // epilogue: bias (+ReLU), fp32 store
    const int col = colBase + tx * 8;
    float bs[8];
    #pragma unroll
    for (int j = 0; j < 8; j++) bs[j] = p.bias[col + j];

    #pragma unroll
    for (int i = 0; i < 8; i++) {
        const int r = rowBase + ty * 8 + i;
        if (r >= p.M) break;
        float o[8];
        #pragma unroll
        for (int j = 0; j < 4; j++) unpack2(acc[i][j], o[2 * j], o[2 * j + 1]);
        #pragma unroll
        for (int j = 0; j < 8; j++) {
            o[j] += bs[j];
            if (p.relu) o[j] = fmaxf(o[j], 0.0f);
        }
        *(float4*)(p.C + (size_t)r * DD + col)     = make_float4(o[0], o[1], o[2], o[3]);
        *(float4*)(p.C + (size_t)r * DD + col + 4) = make_float4(o[4], o[5], o[6], o[7]);
    }
}

// -------------------- fused gather + segment-sum over edges ----------------
// aggr[dst[e]] += msg[src[e]]  (vector red.global.add.v4.f32)
__global__ void scatter_add_kernel(const float4* __restrict__ msg,
                                   const int* __restrict__ src,
                                   const int* __restrict__ dst,
                                   float4* __restrict__ aggr, int E) {
    int t = blockIdx.x * blockDim.x + threadIdx.x;
    const int total = E * (DD / 4);
    if (t >= total) return;
    const int e = t >> 6;            // D/4 = 64 float4 per row
    const int c = t & 63;
    const int s = __ldg(&src[e]);
    const int d = __ldg(&dst[e]);
    float4 v = __ldg(&msg[(size_t)s * 64 + c]);
    float4* p = &aggr[(size_t)d * 64 + c];
    asm volatile("red.global.add.v4.f32 [%0], {%1, %2, %3, %4};"
                 :: "l"(p), "f"(v.x), "f"(v.y), "f"(v.z), "f"(v.w)
                 : "memory");
}

// -------------------- host orchestration -----------------------------------
static void run_gemm(const float* A0, const float* A1, const float* A2,
                     const float* W, const float* bias, float* Cmat,
                     int M, int K, int row_xor, int relu) {
    GemmParams p;
    p.A0 = A0; p.A1 = A1; p.A2 = A2;
    p.W = W; p.bias = bias; p.C = Cmat;
    p.M = M; p.K = K; p.row_xor = row_xor; p.relu = relu;
    dim3 grid(2, (M + 127) / 128);
    gemm_kernel<<<grid, 256>>>(p);
}

extern "C" void kernel_launch(void* const* d_in, const int* in_sizes, int n_in,
                              void* d_out, int out_size) {
    // inputs: [l_size, c_size,] l_edge, c_edge, l_emb, c_emb, then 5 MLPs x (W1,b1,W2,b2)
    const int off = n_in - 24;   // 2 if the two scalar sizes are passed, else 0
    const int*   l_edge = (const int*)  d_in[off + 0];
    const int*   c_edge = (const int*)  d_in[off + 1];
    const float* l_emb0 = (const float*)d_in[off + 2];
    const float* c_emb0 = (const float*)d_in[off + 3];
    const float* w[20];
    for (int i = 0; i < 20; i++) w[i] = (const float*)d_in[off + 4 + i];
    // w[0..3]=l2c, w[4..7]=c2l, w[8..11]=l2l, w[12..15]=cu, w[16..19]=lu

    const int E   = in_sizes[off + 0];
    const int Lsz = in_sizes[off + 2] / DD;
    const int Csz = in_sizes[off + 3] / DD;

    float *hid, *lmsg, *cmsg, *l2lb, *aggc, *aggl;
    cudaGetSymbolAddress((void**)&hid,  g_hid);
    cudaGetSymbolAddress((void**)&lmsg, g_lmsg);
    cudaGetSymbolAddress((void**)&cmsg, g_cmsg);
    cudaGetSymbolAddress((void**)&l2lb, g_l2l);
    cudaGetSymbolAddress((void**)&aggc, g_aggc);
    cudaGetSymbolAddress((void**)&aggl, g_aggl);

    float* out = (float*)d_out;
    float* l_out[5];
    float* c_out[5];
    for (int t = 0; t < 5; t++) {
        l_out[t] = out + (size_t)t * Lsz * DD;
        c_out[t] = out + (size_t)5 * Lsz * DD + (size_t)t * Csz * DD;
    }

    // iteration-0 snapshots
    cudaMemcpyAsync(l_out[0], l_emb0, (size_t)Lsz * DD * sizeof(float),
                    cudaMemcpyDeviceToDevice, 0);
    cudaMemcpyAsync(c_out[0], c_emb0, (size_t)Csz * DD * sizeof(float),
                    cudaMemcpyDeviceToDevice, 0);

    const int scat_total  = E * (DD / 4);
    const int scat_blocks = (scat_total + 255) / 256;

    for (int t = 0; t < 4; t++) {
        const float* lt = l_out[t];
        const float* ct = c_out[t];

        // literal -> clause message features: MLP_l2c(l_emb)
        run_gemm(lt,  lt,  lt,  w[0],  w[1],  hid,  Lsz, 256, 0, 1);
        run_gemm(hid, hid, hid, w[2],  w[3],  lmsg, Lsz, 256, 0, 0);

        // clause -> literal message features: MLP_c2l(c_emb)
        run_gemm(ct,  ct,  ct,  w[4],  w[5],  hid,  Csz, 256, 0, 1);
        run_gemm(hid, hid, hid, w[6],  w[7],  cmsg, Csz, 256, 0, 0);

        // literal <-> negation: MLP_l2l(flip(l_emb)) ; flip = row^1 fused in A load
        run_gemm(lt,  lt,  lt,  w[8],  w[9],  hid,  Lsz, 256, 1, 1);
        run_gemm(hid, hid, hid, w[10], w[11], l2lb, Lsz, 256, 0, 0);

        // clause update: aggr_c[c_edge] += lmsg[l_edge]; c' = MLP_cu([c, aggr_c])
        cudaMemsetAsync(aggc, 0, (size_t)Csz * DD * sizeof(float), 0);
        scatter_add_kernel<<<scat_blocks, 256>>>((const float4*)lmsg, l_edge, c_edge,
                                                 (float4*)aggc, E);
        run_gemm(ct,  aggc, aggc, w[12], w[13], hid,        Csz, 512, 0, 1);
        run_gemm(hid, hid,  hid,  w[14], w[15], c_out[t+1], Csz, 256, 0, 0);

        // literal update: aggr_l[l_edge] += cmsg[c_edge]; l' = MLP_lu([l, aggr_l, l2l])
        cudaMemsetAsync(aggl, 0, (size_t)Lsz * DD * sizeof(float), 0);
        scatter_add_kernel<<<scat_blocks, 256>>>((const float4*)cmsg, c_edge, l_edge,
                                                 (float4*)aggl, E);
        run_gemm(lt,  aggl, l2lb, w[16], w[17], hid,        Lsz, 768, 0, 1);
        run_gemm(hid, hid,  hid,  w[18], w[19], l_out[t+1], Lsz, 256, 0, 0);
    }
}

// round 4
// speedup vs baseline: 1.6851x; 1.6851x over previous
#include <cuda_runtime.h>
#include <cuda_bf16.h>
#include <cstdint>

// ---------------------------------------------------------------------------
// GIN_LCG on GB300: GEMMs via tcgen05 bf16x2-split (3-term) with fp32 TMEM
// accumulation; edge scatter via red.global.add.v4.f32.
// tcgen05 paths are gated on the arch-SPECIFIC feature macro so the harness's
// base-sm_103 compile pass (which rejects tcgen05) builds a correct fp32
// SIMT fallback instead.
// Output layout: l_embs [5][L][256] then c_embs [5][C][256], fp32.
// ---------------------------------------------------------------------------

#if defined(__CUDA_ARCH_FEAT_SM103_ALL) || defined(__CUDA_ARCH_FEAT_SM100_ALL) || \
    defined(__CUDA_ARCH_FEAT_SM101_ALL) || defined(__CUDA_ARCH_FEAT_SM110_ALL)
#define HAS_TC 1
#else
#define HAS_TC 0
#endif

#define DD 256
#define MAX_L 100000
#define MAX_C 50000

// -------------------- device scratch (no allocs allowed) -------------------
__device__ float g_hid [(size_t)MAX_L * DD];
__device__ float g_lmsg[(size_t)MAX_L * DD];
__device__ float g_cmsg[(size_t)MAX_C * DD];
__device__ float g_l2l [(size_t)MAX_L * DD];
__device__ float g_aggc[(size_t)MAX_C * DD];
__device__ float g_aggl[(size_t)MAX_L * DD];
// transposed split weights: [N,K] bf16, hi and lo
__device__ __nv_bfloat16 g_wth[851968];
__device__ __nv_bfloat16 g_wtl[851968];

// -------------------- PTX helpers ------------------------------------------
__device__ __forceinline__ uint32_t smem_u32(const void* p) {
    uint32_t a;
    asm("{ .reg .u64 t; cvta.to.shared.u64 t, %1; cvt.u32.u64 %0, t; }"
        : "=r"(a) : "l"(p));
    return a;
}

#if HAS_TC
#define TC_ALLOC(sa, n) \
    asm volatile("tcgen05.alloc.cta_group::1.sync.aligned.shared::cta.b32 [%0], %1;" \
                 :: "r"(sa), "r"((uint32_t)(n)) : "memory")
#define TC_DEALLOC(t, n) \
    asm volatile("tcgen05.dealloc.cta_group::1.sync.aligned.b32 %0, %1;" \
                 :: "r"(t), "r"((uint32_t)(n)))
#define TC_RELINQ() \
    asm volatile("tcgen05.relinquish_alloc_permit.cta_group::1.sync.aligned;")
#define TC_COMMIT(mb) \
    asm volatile("tcgen05.commit.cta_group::1.mbarrier::arrive::one.shared::cluster.b64 [%0];" \
                 :: "r"(mb) : "memory")
#define TC_FENCE_AFTER()  asm volatile("tcgen05.fence::after_thread_sync;" ::: "memory")
#define TC_FENCE_BEFORE() asm volatile("tcgen05.fence::before_thread_sync;" ::: "memory")
#define TC_WAIT_LD()      asm volatile("tcgen05.wait::ld.sync.aligned;" ::: "memory")
#endif

#define FENCE_ASYNC()     asm volatile("fence.proxy.async.shared::cta;" ::: "memory")
#define MBAR_INIT(a, c) \
    asm volatile("mbarrier.init.shared.b64 [%0], %1;" :: "r"(a), "r"((uint32_t)(c)) : "memory")
#define MBAR_INVAL(a) \
    asm volatile("mbarrier.inval.shared.b64 [%0];" :: "r"(a) : "memory")
#define MBAR_WAIT(addr, ph) do {                                               \
    uint32_t _m = (addr); uint32_t _p = (ph);                                  \
    asm volatile("{\n\t.reg .pred P;\n\tWL_%=:\n\t"                            \
        "mbarrier.try_wait.parity.acquire.cta.shared::cta.b64 P, [%0], %1, 0x989680;\n\t" \
        "@P bra.uni WD_%=;\n\tbra.uni WL_%=;\n\tWD_%=:\n\t}"                   \
        :: "r"(_m), "r"(_p) : "memory");                                       \
} while (0)

#if HAS_TC
#define TC_LD_X32(r, ta)                                                       \
    asm volatile("tcgen05.ld.sync.aligned.32x32b.x32.b32 "                     \
        "{%0, %1, %2, %3, %4, %5, %6, %7, "                                    \
        " %8, %9, %10, %11, %12, %13, %14, %15, "                              \
        " %16, %17, %18, %19, %20, %21, %22, %23, "                            \
        " %24, %25, %26, %27, %28, %29, %30, %31}, [%32];"                     \
        : "=r"((r)[0]),  "=r"((r)[1]),  "=r"((r)[2]),  "=r"((r)[3]),           \
          "=r"((r)[4]),  "=r"((r)[5]),  "=r"((r)[6]),  "=r"((r)[7]),           \
          "=r"((r)[8]),  "=r"((r)[9]),  "=r"((r)[10]), "=r"((r)[11]),          \
          "=r"((r)[12]), "=r"((r)[13]), "=r"((r)[14]), "=r"((r)[15]),          \
          "=r"((r)[16]), "=r"((r)[17]), "=r"((r)[18]), "=r"((r)[19]),          \
          "=r"((r)[20]), "=r"((r)[21]), "=r"((r)[22]), "=r"((r)[23]),          \
          "=r"((r)[24]), "=r"((r)[25]), "=r"((r)[26]), "=r"((r)[27]),          \
          "=r"((r)[28]), "=r"((r)[29]), "=r"((r)[30]), "=r"((r)[31])           \
        : "r"(ta))

__device__ __forceinline__ uint64_t smem_desc(uint32_t addr) {
    // SW128 K-major: layout=2, version=1(Blackwell), SBO=64, LBO=1
    const uint64_t base = (uint64_t(2) << 61) | (uint64_t(1) << 46) |
                          (uint64_t(64) << 32) | (uint64_t(1) << 16);
    return base | ((uint64_t)(addr >> 4) & 0x3FFF);
}
__device__ __forceinline__ void mma_f16_ss(uint32_t d, uint64_t ad, uint64_t bd,
                                           uint32_t idesc, bool accum) {
    uint32_t en = accum ? 1u : 0u;
    asm volatile(
        "{\n\t.reg .pred p;\n\tsetp.ne.u32 p, %5, 0;\n\t"
        "tcgen05.mma.cta_group::1.kind::f16 [%0], %1, %2, %3, {%4, %4, %4, %4}, p;\n\t}"
        :: "r"(d), "l"(ad), "l"(bd), "r"(idesc), "r"(0u), "r"(en) : "memory");
}
#endif  // HAS_TC

#define SW128(o) ((o) ^ ((((uint32_t)(o)) >> 3) & 0x70))

// idesc: dtype=F32, atype=btype=BF16, N=128, M=128 (cg1)
static constexpr uint32_t IDESC =
    (1u << 4) | (1u << 7) | (1u << 10) | ((128u / 8) << 17) | ((128u / 16) << 24);

// smem: [ctrl 32B][pad to 1024-aligned][stage0 64KB][stage1 64KB]
#define HALF_T      16384
#define STAGE_BYTES (4 * HALF_T)
#define SMEM_TOTAL  (1024 + 2 * STAGE_BYTES)

struct GemmParams {
    const float* A0; const float* A1; const float* A2;   // fp32 K-segments (256 each)
    const __nv_bfloat16* Wh; const __nv_bfloat16* Wl;    // [256, K] transposed split
    const float* bias; float* C;
    int M, K, row_xor, relu;
};

__device__ __forceinline__ uint32_t pkbf(__nv_bfloat16 a, __nv_bfloat16 b) {
    __nv_bfloat162 t(a, b);
    return *reinterpret_cast<uint32_t*>(&t);
}

#if HAS_TC
// load one stage's tiles into regs, (optionally wait for buffer), store to smem
__device__ __forceinline__ void produce_stage(
    const GemmParams& p, char* tilep, uint32_t sb, int s,
    int colBase, int arow_idx, bool valid, int tid, int wait_cnt) {

    const int buf = s & 1;
    char* tb = tilep + buf * STAGE_BYTES;
    const int k0  = s * 64;
    const int seg = k0 >> 8;
    const float* Aseg = (seg == 0) ? p.A0 : ((seg == 1) ? p.A1 : p.A2);
    const int kc = k0 & 255;
    const int r  = tid >> 1;       // 0..127
    const int h  = tid & 1;        // half: cols [h*32, h*32+32)

    float4 av[8];
    const float* ap = Aseg + (size_t)arow_idx * DD + kc + h * 32;
    #pragma unroll
    for (int j = 0; j < 8; j++)
        av[j] = valid ? __ldg((const float4*)(ap + j * 4))
                      : make_float4(0.f, 0.f, 0.f, 0.f);

    uint4 bhv[4], blv[4];
    const size_t bo = ((size_t)(colBase + r) * p.K + k0 + h * 32) * 2;  // bytes
    #pragma unroll
    for (int j = 0; j < 4; j++)
        bhv[j] = __ldg((const uint4*)((const char*)p.Wh + bo + j * 16));
    #pragma unroll
    for (int j = 0; j < 4; j++)
        blv[j] = __ldg((const uint4*)((const char*)p.Wl + bo + j * 16));

    if (wait_cnt > 0)
        MBAR_WAIT(sb + (buf ? 16 : 8), (uint32_t)((wait_cnt - 1) & 1));

    #pragma unroll
    for (int j = 0; j < 8; j++) {
        const uint32_t off = (uint32_t)(r * 128 + h * 64 + j * 8);
        const uint32_t so  = SW128(off);
        float fx = av[j].x, fy = av[j].y, fz = av[j].z, fw = av[j].w;
        __nv_bfloat16 hx = __float2bfloat16_rn(fx);
        __nv_bfloat16 hy = __float2bfloat16_rn(fy);
        __nv_bfloat16 hz = __float2bfloat16_rn(fz);
        __nv_bfloat16 hw = __float2bfloat16_rn(fw);
        uint2 hi2;
        hi2.x = pkbf(hx, hy); hi2.y = pkbf(hz, hw);
        uint2 lo2;
        lo2.x = pkbf(__float2bfloat16_rn(fx - __bfloat162float(hx)),
                     __float2bfloat16_rn(fy - __bfloat162float(hy)));
        lo2.y = pkbf(__float2bfloat16_rn(fz - __bfloat162float(hz)),
                     __float2bfloat16_rn(fw - __bfloat162float(hw)));
        *(uint2*)(tb + so)          = hi2;   // Ah
        *(uint2*)(tb + HALF_T + so) = lo2;   // Al
    }
    #pragma unroll
    for (int j = 0; j < 4; j++) {
        const uint32_t off = (uint32_t)(r * 128 + h * 64 + j * 16);
        const uint32_t so  = SW128(off);
        *(uint4*)(tb + 2 * HALF_T + so) = bhv[j];   // Bh
        *(uint4*)(tb + 3 * HALF_T + so) = blv[j];   // Bl
    }
    FENCE_ASYNC();
}
#endif  // HAS_TC

__global__ __launch_bounds__(256, 1)
void gemm_tc(GemmParams p) {
#if HAS_TC
    extern __shared__ char smem[];
    const uint32_t sb = smem_u32(smem);
    const uint32_t tbase = (sb + 32 + 1023u) & ~1023u;
    char* tilep = smem + (tbase - sb);
    const int tid = threadIdx.x;
    const int wid = tid >> 5, lid = tid & 31;
    const int colBase = blockIdx.x * 128;        // grid.x = 2
    const int rowBase = blockIdx.y * 128;
    const int nst = p.K / 64;                    // 4, 8, or 12 (even)

    if (wid == 0) TC_ALLOC(sb, 512);
    if (tid == 0) { MBAR_INIT(sb + 8, 1); MBAR_INIT(sb + 16, 1); }
    __syncthreads();
    uint32_t tmem;
    asm volatile("ld.shared.b32 %0, [%1];" : "=r"(tmem) : "r"(sb));

    const int grow = rowBase + (tid >> 1);
    const bool valid = grow < p.M;
    const int arow_idx = grow ^ p.row_xor;

    int cnt[2] = {0, 0};

    produce_stage(p, tilep, sb, 0, colBase, arow_idx, valid, tid, 0);
    __syncthreads();

    for (int s = 0; s < nst; s++) {
        const int buf = s & 1;
        if (tid == 0) {
            const uint32_t tb = tbase + buf * STAGE_BYTES;
            uint64_t dah = smem_desc(tb);
            uint64_t dal = smem_desc(tb + HALF_T);
            uint64_t dbh = smem_desc(tb + 2 * HALF_T);
            uint64_t dbl = smem_desc(tb + 3 * HALF_T);
            #pragma unroll
            for (int sub = 0; sub < 4; sub++) {
                const bool first = (s == 0 && sub == 0);
                mma_f16_ss(tmem, dah + sub * 2, dbh + sub * 2, IDESC, !first);
                mma_f16_ss(tmem, dah + sub * 2, dbl + sub * 2, IDESC, true);
                mma_f16_ss(tmem, dal + sub * 2, dbh + sub * 2, IDESC, true);
            }
            TC_COMMIT(sb + (buf ? 16 : 8));
        }
        cnt[buf]++;   // every thread tracks the (uniform) commit schedule

        if (s + 1 < nst) {
            produce_stage(p, tilep, sb, s + 1, colBase, arow_idx, valid, tid,
                          cnt[(s + 1) & 1]);
            __syncthreads();
        }
    }

    // wait for all MMAs (both buffers' last commits)
    {
        const int lb = (nst - 1) & 1, ob = lb ^ 1;
        MBAR_WAIT(sb + (lb ? 16 : 8), (uint32_t)((cnt[lb] - 1) & 1));
        if (cnt[ob] > 0)
            MBAR_WAIT(sb + (ob ? 16 : 8), (uint32_t)((cnt[ob] - 1) & 1));
    }
    TC_FENCE_AFTER();

    if (wid < 4) {
        const int rr = rowBase + wid * 32 + lid;
        const bool v = rr < p.M;
        float* crow = p.C + (size_t)rr * DD + colBase;
        #pragma unroll
        for (int ch = 0; ch < 4; ch++) {
            uint32_t dr[32];
            TC_LD_X32(dr, tmem + ch * 32);
            TC_WAIT_LD();
            if (v) {
                #pragma unroll
                for (int j = 0; j < 8; j++) {
                    float4 o;
                    const int c = ch * 32 + j * 4;
                    o.x = __uint_as_float(dr[j * 4 + 0]) + __ldg(&p.bias[colBase + c + 0]);
                    o.y = __uint_as_float(dr[j * 4 + 1]) + __ldg(&p.bias[colBase + c + 1]);
                    o.z = __uint_as_float(dr[j * 4 + 2]) + __ldg(&p.bias[colBase + c + 2]);
                    o.w = __uint_as_float(dr[j * 4 + 3]) + __ldg(&p.bias[colBase + c + 3]);
                    if (p.relu) {
                        o.x = fmaxf(o.x, 0.f); o.y = fmaxf(o.y, 0.f);
                        o.z = fmaxf(o.z, 0.f); o.w = fmaxf(o.w, 0.f);
                    }
                    *(float4*)(crow + c) = o;
                }
            }
        }
        TC_FENCE_BEFORE();
    }

    __syncthreads();
    if (tid == 0) { MBAR_INVAL(sb + 8); MBAR_INVAL(sb + 16); }
    __syncthreads();
    if (wid == 0) { TC_RELINQ(); TC_DEALLOC(tmem, 512); }

#else  // ---------------- fp32 SIMT fallback (base-arch cubin) ---------------
    // Correctness safety net: W reconstructed as Wh+Wl (error ~2^-17, OK).
    __shared__ float As[16][132];
    __shared__ float Bs[16][128];

    const int tid = threadIdx.x;
    const int tx  = tid & 15;
    const int ty  = tid >> 4;
    const int colBase = blockIdx.x * 128;
    const int rowBase = blockIdx.y * 128;

    float acc[8][8];
    #pragma unroll
    for (int i = 0; i < 8; i++)
        #pragma unroll
        for (int j = 0; j < 8; j++) acc[i][j] = 0.f;

    const int nt = p.K / 16;
    const int a_row = tid >> 2;
    const int a_c4  = tid & 3;
    const int b_n   = tid >> 1;   // 0..127
    const int b_h   = tid & 1;    // k-half (8 each)

    for (int t = 0; t < nt; t++) {
        const int k0  = t * 16;
        const int seg = k0 >> 8;
        const float* Aseg = (seg == 0) ? p.A0 : ((seg == 1) ? p.A1 : p.A2);
        const int kcol = (k0 & 255) + a_c4 * 4;
        #pragma unroll
        for (int i = 0; i < 2; i++) {
            const int r = rowBase + a_row + i * 64;
            float4 a4 = make_float4(0.f, 0.f, 0.f, 0.f);
            if (r < p.M)
                a4 = *(const float4*)(Aseg + (size_t)(r ^ p.row_xor) * DD + kcol);
            As[a_c4 * 4 + 0][a_row + i * 64] = a4.x;
            As[a_c4 * 4 + 1][a_row + i * 64] = a4.y;
            As[a_c4 * 4 + 2][a_row + i * 64] = a4.z;
            As[a_c4 * 4 + 3][a_row + i * 64] = a4.w;
        }
        {
            const size_t wo = (size_t)(colBase + b_n) * p.K + k0 + b_h * 8;
            const __nv_bfloat16* wh = p.Wh + wo;
            const __nv_bfloat16* wl = p.Wl + wo;
            #pragma unroll
            for (int j = 0; j < 8; j++)
                Bs[b_h * 8 + j][b_n] =
                    __bfloat162float(wh[j]) + __bfloat162float(wl[j]);
        }
        __syncthreads();
        #pragma unroll
        for (int k = 0; k < 16; k++) {
            float a[8], b[8];
            #pragma unroll
            for (int i = 0; i < 8; i++) a[i] = As[k][ty * 8 + i];
            #pragma unroll
            for (int j = 0; j < 8; j++) b[j] = Bs[k][tx * 8 + j];
            #pragma unroll
            for (int i = 0; i < 8; i++)
                #pragma unroll
                for (int j = 0; j < 8; j++)
                    acc[i][j] = fmaf(a[i], b[j], acc[i][j]);
        }
        __syncthreads();
    }

    const int col = colBase + tx * 8;
    #pragma unroll
    for (int i = 0; i < 8; i++) {
        const int r = rowBase + ty * 8 + i;
        if (r >= p.M) break;
        #pragma unroll
        for (int j = 0; j < 8; j++) {
            float o = acc[i][j] + p.bias[col + j];
            if (p.relu) o = fmaxf(o, 0.f);
            p.C[(size_t)r * DD + col + j] = o;
        }
    }
#endif
}

// -------------------- weight transpose + bf16 split ------------------------
__global__ void wsplit_kernel(const float* __restrict__ W,
                              __nv_bfloat16* __restrict__ oh,
                              __nv_bfloat16* __restrict__ ol, int K, int N) {
    const int idx = blockIdx.x * blockDim.x + threadIdx.x;
    if (idx >= K * N) return;
    const int n = idx / K;
    const int k = idx - n * K;
    const float x = W[(size_t)k * N + n];
    const __nv_bfloat16 hi = __float2bfloat16_rn(x);
    oh[idx] = hi;
    ol[idx] = __float2bfloat16_rn(x - __bfloat162float(hi));
}

// -------------------- fused gather + segment-sum over edges ----------------
__global__ void scatter_add_kernel(const float4* __restrict__ msg,
                                   const int* __restrict__ src,
                                   const int* __restrict__ dst,
                                   float4* __restrict__ aggr, int E) {
    int t = blockIdx.x * blockDim.x + threadIdx.x;
    const int total = E * (DD / 4);
    if (t >= total) return;
    const int e = t >> 6;
    const int c = t & 63;
    const int s = __ldg(&src[e]);
    const int d = __ldg(&dst[e]);
    float4 v = __ldg(&msg[(size_t)s * 64 + c]);
    float4* p = &aggr[(size_t)d * 64 + c];
    asm volatile("red.global.add.v4.f32 [%0], {%1, %2, %3, %4};"
                 :: "l"(p), "f"(v.x), "f"(v.y), "f"(v.z), "f"(v.w)
                 : "memory");
}

// -------------------- host orchestration -----------------------------------
static void run_gemm(const float* A0, const float* A1, const float* A2,
                     const __nv_bfloat16* Wh, const __nv_bfloat16* Wl,
                     const float* bias, float* C, int M, int K,
                     int row_xor, int relu) {
    GemmParams p;
    p.A0 = A0; p.A1 = A1; p.A2 = A2;
    p.Wh = Wh; p.Wl = Wl; p.bias = bias; p.C = C;
    p.M = M; p.K = K; p.row_xor = row_xor; p.relu = relu;
    dim3 grid(2, (M + 127) / 128);
    gemm_tc<<<grid, 256, SMEM_TOTAL>>>(p);
}

extern "C" void kernel_launch(void* const* d_in, const int* in_sizes, int n_in,
                              void* d_out, int out_size) {
    const int off = n_in - 24;
    const int*   l_edge = (const int*)  d_in[off + 0];
    const int*   c_edge = (const int*)  d_in[off + 1];
    const float* l_emb0 = (const float*)d_in[off + 2];
    const float* c_emb0 = (const float*)d_in[off + 3];
    const float* w[20];
    for (int i = 0; i < 20; i++) w[i] = (const float*)d_in[off + 4 + i];
    // w[0..3]=l2c, w[4..7]=c2l, w[8..11]=l2l, w[12..15]=cu, w[16..19]=lu

    const int E   = in_sizes[off + 0];
    const int Lsz = in_sizes[off + 2] / DD;
    const int Csz = in_sizes[off + 3] / DD;

    float *hid, *lmsg, *cmsg, *l2lb, *aggc, *aggl;
    cudaGetSymbolAddress((void**)&hid,  g_hid);
    cudaGetSymbolAddress((void**)&lmsg, g_lmsg);
    cudaGetSymbolAddress((void**)&cmsg, g_cmsg);
    cudaGetSymbolAddress((void**)&l2lb, g_l2l);
    cudaGetSymbolAddress((void**)&aggc, g_aggc);
    cudaGetSymbolAddress((void**)&aggl, g_aggl);
    __nv_bfloat16 *wth, *wtl;
    cudaGetSymbolAddress((void**)&wth, g_wth);
    cudaGetSymbolAddress((void**)&wtl, g_wtl);

    cudaFuncSetAttribute(gemm_tc, cudaFuncAttributeMaxDynamicSharedMemorySize,
                         SMEM_TOTAL);

    // transpose + split all 10 weight matrices into bf16 hi/lo [N,K]
    static const size_t woff[10] = {0, 65536, 131072, 196608, 262144, 327680,
                                    393216, 524288, 589824, 786432};
    static const int    wKs [10] = {256, 256, 256, 256, 256, 256, 512, 256, 768, 256};
    static const int    wsrc[10] = {0, 2, 4, 6, 8, 10, 12, 14, 16, 18};
    for (int i = 0; i < 10; i++) {
        const int total = wKs[i] * 256;
        wsplit_kernel<<<(total + 255) / 256, 256>>>(w[wsrc[i]], wth + woff[i],
                                                    wtl + woff[i], wKs[i], 256);
    }

    float* out = (float*)d_out;
    float* l_out[5];
    float* c_out[5];
    for (int t = 0; t < 5; t++) {
        l_out[t] = out + (size_t)t * Lsz * DD;
        c_out[t] = out + (size_t)5 * Lsz * DD + (size_t)t * Csz * DD;
    }

    cudaMemcpyAsync(l_out[0], l_emb0, (size_t)Lsz * DD * sizeof(float),
                    cudaMemcpyDeviceToDevice, 0);
    cudaMemcpyAsync(c_out[0], c_emb0, (size_t)Csz * DD * sizeof(float),
                    cudaMemcpyDeviceToDevice, 0);

    const int scat_total  = E * (DD / 4);
    const int scat_blocks = (scat_total + 255) / 256;

    #define WH(i) (wth + woff[i])
    #define WL(i) (wtl + woff[i])

    for (int t = 0; t < 4; t++) {
        const float* lt = l_out[t];
        const float* ct = c_out[t];

        // l2c message features
        run_gemm(lt,  lt,  lt,  WH(0), WL(0), w[1],  hid,  Lsz, 256, 0, 1);
        run_gemm(hid, hid, hid, WH(1), WL(1), w[3],  lmsg, Lsz, 256, 0, 0);

        // c2l message features
        run_gemm(ct,  ct,  ct,  WH(2), WL(2), w[5],  hid,  Csz, 256, 0, 1);
        run_gemm(hid, hid, hid, WH(3), WL(3), w[7],  cmsg, Csz, 256, 0, 0);

        // l2l: MLP(flip(l_emb)); flip fused via row^1
        run_gemm(lt,  lt,  lt,  WH(4), WL(4), w[9],  hid,  Lsz, 256, 1, 1);
        run_gemm(hid, hid, hid, WH(5), WL(5), w[11], l2lb, Lsz, 256, 0, 0);

        // clause update
        cudaMemsetAsync(aggc, 0, (size_t)Csz * DD * sizeof(float), 0);
        scatter_add_kernel<<<scat_blocks, 256>>>((const float4*)lmsg, l_edge,
                                                 c_edge, (float4*)aggc, E);
        run_gemm(ct,  aggc, aggc, WH(6), WL(6), w[13], hid,        Csz, 512, 0, 1);
        run_gemm(hid, hid,  hid,  WH(7), WL(7), w[15], c_out[t+1], Csz, 256, 0, 0);

        // literal update
        cudaMemsetAsync(aggl, 0, (size_t)Lsz * DD * sizeof(float), 0);
        scatter_add_kernel<<<scat_blocks, 256>>>((const float4*)cmsg, c_edge,
                                                 l_edge, (float4*)aggl, E);
        run_gemm(lt,  aggl, l2lb, WH(8), WL(8), w[17], hid,        Lsz, 768, 0, 1);
        run_gemm(hid, hid,  hid,  WH(9), WL(9), w[19], l_out[t+1], Lsz, 256, 0, 0);
    }
    #undef WH
    #undef WL
}